// round 2
// baseline (speedup 1.0000x reference)
#include <cuda_runtime.h>

// Problem constants
#define NN   512   // nodes
#define CC   64    // channels
#define RR   32    // rbf
#define MM   5     // mlps
#define BT   32    // b-tile
#define NTHREADS 256

// Shared memory layout (floats)
#define OFF_W1   0        // [5][32][64] = 10240
#define OFF_B1   10240    // [5][64]     = 320
#define OFF_W2   10560    // [5][64][64] = 20480  (reused as partial-sum buffer at end)
#define OFF_B2   31040    // [5][64]     = 320
#define OFF_RBF  31360    // [32][33]    = 1056
#define OFF_H    32416    // [32][325]   = 10400
#define OFF_X0   42816    // [32][65]    = 2080
#define OFF_X1   44896    // [3][32][65] = 6240
#define OFF_U    51136    // [32][4]     = 128
#define SMEM_FLOATS 51264
#define SMEM_BYTES (SMEM_FLOATS * 4)

#define H_STRIDE 325

extern __shared__ float smem[];

__global__ __launch_bounds__(NTHREADS, 1)
void conv_tfn_kernel(const float* __restrict__ gx0,
                     const float* __restrict__ gx1,
                     const float* __restrict__ grbf,
                     const float* __restrict__ gu,
                     const float* __restrict__ gw1,
                     const float* __restrict__ gb1,
                     const float* __restrict__ gw2,
                     const float* __restrict__ gb2,
                     float* __restrict__ out)
{
    const int a   = blockIdx.x;
    const int tid = threadIdx.x;

    float* sW1  = smem + OFF_W1;
    float* sB1  = smem + OFF_B1;
    float* sW2  = smem + OFF_W2;
    float* sB2  = smem + OFF_B2;
    float* sRBF = smem + OFF_RBF;
    float* sH   = smem + OFF_H;
    float* sX0  = smem + OFF_X0;
    float* sX1  = smem + OFF_X1;
    float* sU   = smem + OFF_U;

    // ---- load weights (once per block) ----
    for (int i = tid; i < MM*RR*CC; i += NTHREADS) sW1[i] = gw1[i];
    for (int i = tid; i < MM*CC*CC; i += NTHREADS) sW2[i] = gw2[i];
    for (int i = tid; i < MM*CC;    i += NTHREADS) { sB1[i] = gb1[i]; sB2[i] = gb2[i]; }

    // thread tile: 2 b's x 4 f's
    const int fb = tid & 15;        // 0..15
    const int f0 = fb * 4;          // channel base
    const int bb = tid >> 4;        // 0..15
    const int b0 = bb * 2;          // local b base

    // persistent output accumulators: [k(f)][comp]
    // comp: 0=o00, 1=o11_0, 2..4=o01, 5..7=o10, 8..10=o11_1
    float acc[4][11];
    #pragma unroll
    for (int k = 0; k < 4; k++)
        #pragma unroll
        for (int c = 0; c < 11; c++) acc[k][c] = 0.0f;

    for (int bt = 0; bt < NN; bt += BT) {
        __syncthreads();   // previous iteration's readers done before we overwrite tiles

        // ---- stage tiles ----
        {
            const float* p = grbf + (size_t)a * NN * RR + (size_t)bt * RR;
            for (int i = tid; i < BT * RR; i += NTHREADS)
                sRBF[(i >> 5) * 33 + (i & 31)] = p[i];
        }
        {
            const float* p = gx0 + (size_t)bt * CC;
            for (int i = tid; i < BT * CC; i += NTHREADS)
                sX0[(i >> 6) * 65 + (i & 63)] = p[i];
        }
        {
            const float* p = gx1 + (size_t)bt * CC * 3;
            for (int i = tid; i < BT * CC * 3; i += NTHREADS) {
                int bl  = i / 192;
                int rem = i - bl * 192;
                int f   = rem / 3;
                int c   = rem - f * 3;
                sX1[c * (BT * 65) + bl * 65 + f] = p[i];
            }
        }
        if (tid < BT * 3) {
            const float* p = gu + (size_t)a * NN * 3 + (size_t)bt * 3;
            int bl = tid / 3;
            int c  = tid - bl * 3;
            sU[bl * 4 + c] = p[tid];
        }
        __syncthreads();

        // ---- GEMM1: H[b][m*64+f] = relu(rbf[b,:] @ W1[m] + b1[m]) ----
        {
            float h[2][MM][4];
            #pragma unroll
            for (int bi = 0; bi < 2; bi++)
                #pragma unroll
                for (int m = 0; m < MM; m++)
                    #pragma unroll
                    for (int k = 0; k < 4; k++) h[bi][m][k] = 0.0f;

            #pragma unroll 8
            for (int r = 0; r < RR; r++) {
                float rb0 = sRBF[b0 * 33 + r];
                float rb1 = sRBF[(b0 + 1) * 33 + r];
                #pragma unroll
                for (int m = 0; m < MM; m++) {
                    float4 w = *(const float4*)&sW1[m * (RR*CC) + r * CC + f0];
                    h[0][m][0] = fmaf(rb0, w.x, h[0][m][0]);
                    h[0][m][1] = fmaf(rb0, w.y, h[0][m][1]);
                    h[0][m][2] = fmaf(rb0, w.z, h[0][m][2]);
                    h[0][m][3] = fmaf(rb0, w.w, h[0][m][3]);
                    h[1][m][0] = fmaf(rb1, w.x, h[1][m][0]);
                    h[1][m][1] = fmaf(rb1, w.y, h[1][m][1]);
                    h[1][m][2] = fmaf(rb1, w.z, h[1][m][2]);
                    h[1][m][3] = fmaf(rb1, w.w, h[1][m][3]);
                }
            }
            #pragma unroll
            for (int m = 0; m < MM; m++)
                #pragma unroll
                for (int k = 0; k < 4; k++) {
                    float bv = sB1[m * CC + f0 + k];
                    sH[b0 * H_STRIDE + m * CC + f0 + k]       = fmaxf(h[0][m][k] + bv, 0.0f);
                    sH[(b0 + 1) * H_STRIDE + m * CC + f0 + k] = fmaxf(h[1][m][k] + bv, 0.0f);
                }
        }
        __syncthreads();

        // ---- GEMM2 + fused contraction, per MLP m ----
        const bool skip0 = (bt + b0 == a);
        const bool skip1 = (bt + b0 + 1 == a);

        #pragma unroll
        for (int m = 0; m < MM; m++) {
            float r2[2][4];
            #pragma unroll
            for (int bi = 0; bi < 2; bi++)
                #pragma unroll
                for (int k = 0; k < 4; k++) r2[bi][k] = 0.0f;

            #pragma unroll 16
            for (int c = 0; c < CC; c++) {
                float h0 = sH[b0 * H_STRIDE + m * CC + c];
                float h1 = sH[(b0 + 1) * H_STRIDE + m * CC + c];
                float4 w = *(const float4*)&sW2[m * (CC*CC) + c * CC + f0];
                r2[0][0] = fmaf(h0, w.x, r2[0][0]);
                r2[0][1] = fmaf(h0, w.y, r2[0][1]);
                r2[0][2] = fmaf(h0, w.z, r2[0][2]);
                r2[0][3] = fmaf(h0, w.w, r2[0][3]);
                r2[1][0] = fmaf(h1, w.x, r2[1][0]);
                r2[1][1] = fmaf(h1, w.y, r2[1][1]);
                r2[1][2] = fmaf(h1, w.z, r2[1][2]);
                r2[1][3] = fmaf(h1, w.w, r2[1][3]);
            }

            #pragma unroll
            for (int bi = 0; bi < 2; bi++) {
                if (bi == 0 ? skip0 : skip1) continue;   // diagonal mask (zeroes biased rad)
                const int bl = b0 + bi;
                const float u0 = sU[bl * 4 + 0];
                const float u1 = sU[bl * 4 + 1];
                const float u2 = sU[bl * 4 + 2];
                #pragma unroll
                for (int k = 0; k < 4; k++) {
                    const float rad = r2[bi][k] + sB2[m * CC + f0 + k];
                    if (m == 0) {
                        acc[k][0] = fmaf(rad, sX0[bl * 65 + f0 + k], acc[k][0]);
                    } else if (m == 1) {
                        float t = rad * sX0[bl * 65 + f0 + k];
                        acc[k][2] = fmaf(u0, t, acc[k][2]);
                        acc[k][3] = fmaf(u1, t, acc[k][3]);
                        acc[k][4] = fmaf(u2, t, acc[k][4]);
                    } else {
                        const float xx = sX1[0 * (BT*65) + bl * 65 + f0 + k];
                        const float xy = sX1[1 * (BT*65) + bl * 65 + f0 + k];
                        const float xz = sX1[2 * (BT*65) + bl * 65 + f0 + k];
                        if (m == 2) {
                            acc[k][5] = fmaf(rad, xx, acc[k][5]);
                            acc[k][6] = fmaf(rad, xy, acc[k][6]);
                            acc[k][7] = fmaf(rad, xz, acc[k][7]);
                        } else if (m == 3) {
                            float dot = u0 * xx + u1 * xy + u2 * xz;
                            acc[k][1] = fmaf(rad, dot, acc[k][1]);
                        } else {  // m == 4 : cross product (u x x1)
                            float cx = u1 * xz - u2 * xy;
                            float cy = u2 * xx - u0 * xz;
                            float cz = u0 * xy - u1 * xx;
                            acc[k][8]  = fmaf(rad, cx, acc[k][8]);
                            acc[k][9]  = fmaf(rad, cy, acc[k][9]);
                            acc[k][10] = fmaf(rad, cz, acc[k][10]);
                        }
                    }
                }
            }
        }
    }

    // ---- cross-thread reduction over the 16 b-groups ----
    __syncthreads();
    float* sPart = sW2;   // weights no longer needed; 16*16*48 = 12288 floats < 20480
    {
        const int base = (bb * 16 + fb) * 48;
        #pragma unroll
        for (int k = 0; k < 4; k++)
            #pragma unroll
            for (int c = 0; c < 11; c++)
                sPart[base + k * 11 + c] = acc[k][c];
    }
    __syncthreads();

    const float nm = rsqrtf((float)(NN - 1));
    float* out1 = out + NN * 2 * CC;   // out0 is [512,128,1] = 65536 floats

    for (int idx = tid; idx < CC * 11; idx += NTHREADS) {
        const int f    = idx / 11;
        const int comp = idx - f * 11;
        const int fb2  = f >> 2;
        const int k    = f & 3;
        float s = 0.0f;
        #pragma unroll
        for (int g = 0; g < 16; g++)
            s += sPart[(g * 16 + fb2) * 48 + k * 11 + comp];
        s *= nm;

        if (comp == 0)       out[a * 128 + f]                       = s;  // o00
        else if (comp == 1)  out[a * 128 + 64 + f]                  = s;  // o11_0
        else if (comp < 5)   out1[a * 576 + f * 3 + (comp - 2)]     = s;  // o01
        else if (comp < 8)   out1[a * 576 + (64 + f) * 3 + (comp-5)] = s; // o10
        else                 out1[a * 576 + (128 + f) * 3 + (comp-8)] = s;// o11_1
    }
}

extern "C" void kernel_launch(void* const* d_in, const int* in_sizes, int n_in,
                              void* d_out, int out_size) {
    const float* x0  = (const float*)d_in[0];
    const float* x1  = (const float*)d_in[1];
    const float* rbf = (const float*)d_in[2];
    const float* u   = (const float*)d_in[3];
    // d_in[4] = r_ij : unused (switching_fn == None)
    const float* w1  = (const float*)d_in[5];
    const float* b1  = (const float*)d_in[6];
    const float* w2  = (const float*)d_in[7];
    const float* b2  = (const float*)d_in[8];
    float* out = (float*)d_out;

    cudaFuncSetAttribute(conv_tfn_kernel,
                         cudaFuncAttributeMaxDynamicSharedMemorySize, SMEM_BYTES);

    conv_tfn_kernel<<<NN, NTHREADS, SMEM_BYTES>>>(x0, x1, rbf, u, w1, b1, w2, b2, out);
}